// round 1
// baseline (speedup 1.0000x reference)
#include <cuda_runtime.h>

// LDDMM variational shooting RHS, Gaussian kernel, sigma = 0.1.
//   p = clamp(mom, -1, 1)
//   K_ij = exp(-|x_i - x_j|^2 / (2 sig^2))
//   dcp_i  = sum_j K_ij p_j
//   dmom_i = (1/sig^2) sum_j K_ij (p_i . p_j) (x_i - x_j)
// Output layout: [dmom (N*3) | dcp (N*3)]  (tuple order of the reference).

#define TPB   256
#define JTILE 512

__global__ void zero_out_kernel(float* __restrict__ out, int n) {
    int i = blockIdx.x * blockDim.x + threadIdx.x;
    if (i < n) out[i] = 0.0f;
}

__global__ __launch_bounds__(TPB)
void lddmm_kernel(const float* __restrict__ mom,
                  const float* __restrict__ x,
                  float* __restrict__ out,
                  int N)
{
    __shared__ float sx[JTILE * 3];
    __shared__ float sp[JTILE * 3];

    const int j0 = blockIdx.y * JTILE;
    const int jcount = min(JTILE, N - j0);

    // Cooperative load of the j-tile (positions + clamped momenta).
    for (int k = threadIdx.x; k < jcount * 3; k += TPB) {
        sx[k] = x[j0 * 3 + k];
        float m = mom[j0 * 3 + k];
        sp[k] = fminf(1.0f, fmaxf(-1.0f, m));
    }
    __syncthreads();

    const int i = blockIdx.x * TPB + threadIdx.x;
    if (i >= N) return;

    const float xi0 = x[3 * i + 0];
    const float xi1 = x[3 * i + 1];
    const float xi2 = x[3 * i + 2];
    const float pi0 = fminf(1.0f, fmaxf(-1.0f, mom[3 * i + 0]));
    const float pi1 = fminf(1.0f, fmaxf(-1.0f, mom[3 * i + 1]));
    const float pi2 = fminf(1.0f, fmaxf(-1.0f, mom[3 * i + 2]));

    float ac0 = 0.f, ac1 = 0.f, ac2 = 0.f;   // dcp accumulator (K @ p)
    float am0 = 0.f, am1 = 0.f, am2 = 0.f;   // dmom accumulator (sum w * (xi - xj))

    #pragma unroll 8
    for (int jj = 0; jj < jcount; jj++) {
        const float dx0 = xi0 - sx[3 * jj + 0];
        const float dx1 = xi1 - sx[3 * jj + 1];
        const float dx2 = xi2 - sx[3 * jj + 2];
        const float d2  = dx0 * dx0 + dx1 * dx1 + dx2 * dx2;
        // exp(-d2 / (2 * 0.01)) = exp(-50 * d2)
        const float e = __expf(d2 * -50.0f);
        const float pj0 = sp[3 * jj + 0];
        const float pj1 = sp[3 * jj + 1];
        const float pj2 = sp[3 * jj + 2];
        const float pd = pi0 * pj0 + pi1 * pj1 + pi2 * pj2;
        const float w  = e * pd;
        ac0 += e * pj0;  ac1 += e * pj1;  ac2 += e * pj2;
        am0 += w * dx0;  am1 += w * dx1;  am2 += w * dx2;
    }

    const float inv_sig2 = 100.0f;  // 1 / sigma^2, sigma = 0.1
    atomicAdd(&out[3 * i + 0], inv_sig2 * am0);
    atomicAdd(&out[3 * i + 1], inv_sig2 * am1);
    atomicAdd(&out[3 * i + 2], inv_sig2 * am2);
    float* dcp = out + 3 * N;
    atomicAdd(&dcp[3 * i + 0], ac0);
    atomicAdd(&dcp[3 * i + 1], ac1);
    atomicAdd(&dcp[3 * i + 2], ac2);
}

extern "C" void kernel_launch(void* const* d_in, const int* in_sizes, int n_in,
                              void* d_out, int out_size) {
    const float* mom = (const float*)d_in[0];
    const float* x   = (const float*)d_in[1];
    float* out = (float*)d_out;
    const int N = in_sizes[0] / 3;

    zero_out_kernel<<<(out_size + 255) / 256, 256>>>(out, out_size);

    dim3 grid((N + TPB - 1) / TPB, (N + JTILE - 1) / JTILE);
    lddmm_kernel<<<grid, TPB>>>(mom, x, out, N);
}

// round 4
// speedup vs baseline: 1.2508x; 1.2508x over previous
#include <cuda_runtime.h>

// LDDMM variational shooting RHS, Gaussian kernel, sigma = 0.1.
//   p = clamp(mom, -1, 1)
//   K_ij = exp(-|x_i - x_j|^2 / (2 sig^2)) = exp2(-50*log2(e) * d2)
//   dcp_i  = sum_j K_ij p_j
//   dmom_i = (1/sig^2) sum_j K_ij (p_i . p_j) (x_i - x_j)
// Output layout: [dmom (N*3) | dcp (N*3)].
//
// Issue-bound kernel -> cut issued instrs/pair:
//  - packed f32x2 fma/add/mul (PTX-only on sm_103a), 2 j's per packed lane
//  - 4 j's per loop iteration, j-tile read via broadcast LDS.128 (ulonglong2)
//  - SoA shared layout, x stored negated so dx = one packed add

#define TPB    256
#define JTILE  512

typedef unsigned long long u64;

__device__ __forceinline__ u64 f2pack(float lo, float hi) {
    u64 r; asm("mov.b64 %0, {%1, %2};" : "=l"(r) : "f"(lo), "f"(hi)); return r;
}
__device__ __forceinline__ void f2unpack(u64 v, float& lo, float& hi) {
    asm("mov.b64 {%0, %1}, %2;" : "=f"(lo), "=f"(hi) : "l"(v));
}
__device__ __forceinline__ u64 fma2(u64 a, u64 b, u64 c) {
    u64 d; asm("fma.rn.f32x2 %0, %1, %2, %3;" : "=l"(d) : "l"(a), "l"(b), "l"(c)); return d;
}
__device__ __forceinline__ u64 add2(u64 a, u64 b) {
    u64 d; asm("add.rn.f32x2 %0, %1, %2;" : "=l"(d) : "l"(a), "l"(b)); return d;
}
__device__ __forceinline__ u64 mul2(u64 a, u64 b) {
    u64 d; asm("mul.rn.f32x2 %0, %1, %2;" : "=l"(d) : "l"(a), "l"(b)); return d;
}
__device__ __forceinline__ float ex2(float x) {
    float r; asm("ex2.approx.f32 %0, %1;" : "=f"(r) : "f"(x)); return r;
}

__global__ void zero_out_kernel(float* __restrict__ out, int n) {
    int i = blockIdx.x * blockDim.x + threadIdx.x;
    if (i < n) out[i] = 0.0f;
}

__global__ __launch_bounds__(TPB)
void lddmm_kernel(const float* __restrict__ mom,
                  const float* __restrict__ x,
                  float* __restrict__ out,
                  int N)
{
    // SoA tiles: negated x (so dx = xi + (-xj) is one packed add), clamped p.
    __shared__ __align__(16) float snx0[JTILE], snx1[JTILE], snx2[JTILE];
    __shared__ __align__(16) float sp0[JTILE], sp1[JTILE], sp2[JTILE];

    const int j0 = blockIdx.y * JTILE;
    const int jcount = min(JTILE, N - j0);

    for (int j = threadIdx.x; j < jcount; j += TPB) {
        const int g = j0 + j;
        snx0[j] = -x[3 * g + 0];
        snx1[j] = -x[3 * g + 1];
        snx2[j] = -x[3 * g + 2];
        sp0[j] = fminf(1.0f, fmaxf(-1.0f, mom[3 * g + 0]));
        sp1[j] = fminf(1.0f, fmaxf(-1.0f, mom[3 * g + 1]));
        sp2[j] = fminf(1.0f, fmaxf(-1.0f, mom[3 * g + 2]));
    }
    __syncthreads();

    const int i = blockIdx.x * TPB + threadIdx.x;
    if (i >= N) return;

    const float xi0 = x[3 * i + 0];
    const float xi1 = x[3 * i + 1];
    const float xi2 = x[3 * i + 2];
    const float pi0 = fminf(1.0f, fmaxf(-1.0f, mom[3 * i + 0]));
    const float pi1 = fminf(1.0f, fmaxf(-1.0f, mom[3 * i + 1]));
    const float pi2 = fminf(1.0f, fmaxf(-1.0f, mom[3 * i + 2]));

    const u64 xi0_2 = f2pack(xi0, xi0);
    const u64 xi1_2 = f2pack(xi1, xi1);
    const u64 xi2_2 = f2pack(xi2, xi2);
    const u64 pi0_2 = f2pack(pi0, pi0);
    const u64 pi1_2 = f2pack(pi1, pi1);
    const u64 pi2_2 = f2pack(pi2, pi2);
    // exp(-50*d2) = exp2(d2 * (-50 * log2(e)))
    const float CE = -72.13475204444817f;
    const u64 cexp = f2pack(CE, CE);

    u64 ac0 = 0, ac1 = 0, ac2 = 0;  // dcp accumulators (packed pairs)
    u64 am0 = 0, am1 = 0, am2 = 0;  // dmom accumulators

    const int jquads = jcount >> 2;
    #pragma unroll 2
    for (int q = 0; q < jquads; q++) {
        // Broadcast LDS.128: four consecutive j values per coordinate,
        // delivered as two packed f32x2 registers each.
        const ulonglong2 nx0q = *(const ulonglong2*)&snx0[4 * q];
        const ulonglong2 nx1q = *(const ulonglong2*)&snx1[4 * q];
        const ulonglong2 nx2q = *(const ulonglong2*)&snx2[4 * q];
        const ulonglong2 pj0q = *(const ulonglong2*)&sp0[4 * q];
        const ulonglong2 pj1q = *(const ulonglong2*)&sp1[4 * q];
        const ulonglong2 pj2q = *(const ulonglong2*)&sp2[4 * q];

        #pragma unroll
        for (int h = 0; h < 2; h++) {
            const u64 nx0 = h ? nx0q.y : nx0q.x;
            const u64 nx1 = h ? nx1q.y : nx1q.x;
            const u64 nx2 = h ? nx2q.y : nx2q.x;
            const u64 pj0 = h ? pj0q.y : pj0q.x;
            const u64 pj1 = h ? pj1q.y : pj1q.x;
            const u64 pj2 = h ? pj2q.y : pj2q.x;

            const u64 dx0 = add2(xi0_2, nx0);
            const u64 dx1 = add2(xi1_2, nx1);
            const u64 dx2 = add2(xi2_2, nx2);
            u64 d2 = mul2(dx0, dx0);
            d2 = fma2(dx1, dx1, d2);
            d2 = fma2(dx2, dx2, d2);

            const u64 targ = mul2(d2, cexp);
            float tlo, thi;
            f2unpack(targ, tlo, thi);
            const u64 e = f2pack(ex2(tlo), ex2(thi));

            u64 pd = mul2(pi0_2, pj0);
            pd = fma2(pi1_2, pj1, pd);
            pd = fma2(pi2_2, pj2, pd);
            const u64 w = mul2(e, pd);

            ac0 = fma2(e, pj0, ac0);
            ac1 = fma2(e, pj1, ac1);
            ac2 = fma2(e, pj2, ac2);
            am0 = fma2(w, dx0, am0);
            am1 = fma2(w, dx1, am1);
            am2 = fma2(w, dx2, am2);
        }
    }

    // Scalar tail (jcount % 4; not hit for N=8192 with JTILE=512).
    float tc0 = 0.f, tc1 = 0.f, tc2 = 0.f, tm0 = 0.f, tm1 = 0.f, tm2 = 0.f;
    for (int jj = jquads << 2; jj < jcount; jj++) {
        const float dx0 = xi0 + snx0[jj];
        const float dx1 = xi1 + snx1[jj];
        const float dx2 = xi2 + snx2[jj];
        const float d2 = dx0 * dx0 + dx1 * dx1 + dx2 * dx2;
        const float e = ex2(d2 * CE);
        const float pj0 = sp0[jj], pj1 = sp1[jj], pj2 = sp2[jj];
        const float pd = pi0 * pj0 + pi1 * pj1 + pi2 * pj2;
        const float w = e * pd;
        tc0 += e * pj0;  tc1 += e * pj1;  tc2 += e * pj2;
        tm0 += w * dx0;  tm1 += w * dx1;  tm2 += w * dx2;
    }

    float a, b;
    const float inv_sig2 = 100.0f;  // 1 / sigma^2
    f2unpack(am0, a, b); atomicAdd(&out[3 * i + 0], inv_sig2 * (a + b + tm0));
    f2unpack(am1, a, b); atomicAdd(&out[3 * i + 1], inv_sig2 * (a + b + tm1));
    f2unpack(am2, a, b); atomicAdd(&out[3 * i + 2], inv_sig2 * (a + b + tm2));
    float* dcp = out + 3 * N;
    f2unpack(ac0, a, b); atomicAdd(&dcp[3 * i + 0], a + b + tc0);
    f2unpack(ac1, a, b); atomicAdd(&dcp[3 * i + 1], a + b + tc1);
    f2unpack(ac2, a, b); atomicAdd(&dcp[3 * i + 2], a + b + tc2);
}

extern "C" void kernel_launch(void* const* d_in, const int* in_sizes, int n_in,
                              void* d_out, int out_size) {
    const float* mom = (const float*)d_in[0];
    const float* x   = (const float*)d_in[1];
    float* out = (float*)d_out;
    const int N = in_sizes[0] / 3;

    zero_out_kernel<<<(out_size + 255) / 256, 256>>>(out, out_size);

    dim3 grid((N + TPB - 1) / TPB, (N + JTILE - 1) / JTILE);
    lddmm_kernel<<<grid, TPB>>>(mom, x, out, N);
}

// round 5
// speedup vs baseline: 1.5114x; 1.2083x over previous
#include <cuda_runtime.h>

// LDDMM variational shooting RHS, Gaussian kernel, sigma = 0.1.
//   p = clamp(mom, -1, 1)
//   K_ij = exp(-50*|xi-xj|^2) = exp2(CE*(|xi|^2+|xj|^2-2 xi.xj)), CE=-50*log2(e)
//   dcp_i  = sum_j K_ij p_j
//   dmom_i = 100 * (xi * sum_j w_ij - sum_j w_ij x_j),  w_ij = K_ij (pi.pj)
// Output layout: [dmom (N*3) | dcp (N*3)].
//
// R5: fma-pipe-cycles x issue-efficiency model.
//  - d2 expansion: no dx needed; exp coefficient folded into per-i/per-j terms
//  - packed f32x2 math (2 j's per op), 4 j's per loop via broadcast LDS.128
//  - 2 i-points per thread: j-loads amortized, 2 independent chains hide
//    MUFU/LDS latency
//  - TPB=128, <=102 regs, grid 736 CTAs ~= one balanced wave at occ 5

#define TPB    128
#define IBLK   2
#define JTILE  360   // ceil(8192/23), divisible by 4; grid.y=23 -> 736 CTAs

typedef unsigned long long u64;

__device__ __forceinline__ u64 f2pack(float lo, float hi) {
    u64 r; asm("mov.b64 %0, {%1, %2};" : "=l"(r) : "f"(lo), "f"(hi)); return r;
}
__device__ __forceinline__ void f2unpack(u64 v, float& lo, float& hi) {
    asm("mov.b64 {%0, %1}, %2;" : "=f"(lo), "=f"(hi) : "l"(v));
}
__device__ __forceinline__ u64 fma2(u64 a, u64 b, u64 c) {
    u64 d; asm("fma.rn.f32x2 %0, %1, %2, %3;" : "=l"(d) : "l"(a), "l"(b), "l"(c)); return d;
}
__device__ __forceinline__ u64 add2(u64 a, u64 b) {
    u64 d; asm("add.rn.f32x2 %0, %1, %2;" : "=l"(d) : "l"(a), "l"(b)); return d;
}
__device__ __forceinline__ u64 mul2(u64 a, u64 b) {
    u64 d; asm("mul.rn.f32x2 %0, %1, %2;" : "=l"(d) : "l"(a), "l"(b)); return d;
}
__device__ __forceinline__ float ex2(float x) {
    float r; asm("ex2.approx.f32 %0, %1;" : "=f"(r) : "f"(x)); return r;
}
__device__ __forceinline__ float clamp1(float v) {
    return fminf(1.0f, fmaxf(-1.0f, v));
}

#define CE   (-72.13475204444817f)   // -50 * log2(e)
#define CEM2 (144.26950408889634f)   // -2 * CE

__global__ void zero_out_kernel(float* __restrict__ out, int n) {
    int i = blockIdx.x * blockDim.x + threadIdx.x;
    if (i < n) out[i] = 0.0f;
}

__global__ __launch_bounds__(TPB, 5)
void lddmm_kernel(const float* __restrict__ mom,
                  const float* __restrict__ x,
                  float* __restrict__ out,
                  int N)
{
    // SoA j-tile: raw x, clamped p, cj = CE*|xj|^2.
    __shared__ __align__(16) float sxj0[JTILE], sxj1[JTILE], sxj2[JTILE];
    __shared__ __align__(16) float spj0[JTILE], spj1[JTILE], spj2[JTILE];
    __shared__ __align__(16) float scj[JTILE];

    const int j0 = blockIdx.y * JTILE;
    const int jcount = min(JTILE, N - j0);

    for (int j = threadIdx.x; j < jcount; j += TPB) {
        const int g = j0 + j;
        const float a = x[3 * g + 0], b = x[3 * g + 1], c = x[3 * g + 2];
        sxj0[j] = a; sxj1[j] = b; sxj2[j] = c;
        scj[j] = CE * (a * a + b * b + c * c);
        spj0[j] = clamp1(mom[3 * g + 0]);
        spj1[j] = clamp1(mom[3 * g + 1]);
        spj2[j] = clamp1(mom[3 * g + 2]);
    }
    __syncthreads();

    const int ibase = blockIdx.x * (TPB * IBLK) + threadIdx.x;

    // Per-i packed constants: A = CE*|xi|^2, XCd = CEM2*xi_d, Pd = clamp(pi_d).
    u64 A[IBLK], XC0[IBLK], XC1[IBLK], XC2[IBLK], P0[IBLK], P1[IBLK], P2[IBLK];
    #pragma unroll
    for (int ii = 0; ii < IBLK; ii++) {
        const int i = ibase + ii * TPB;
        float a = 0.f, b = 0.f, c = 0.f, m0 = 0.f, m1 = 0.f, m2 = 0.f;
        if (i < N) {
            a = x[3 * i + 0]; b = x[3 * i + 1]; c = x[3 * i + 2];
            m0 = clamp1(mom[3 * i + 0]);
            m1 = clamp1(mom[3 * i + 1]);
            m2 = clamp1(mom[3 * i + 2]);
        }
        const float av = CE * (a * a + b * b + c * c);
        A[ii]   = f2pack(av, av);
        XC0[ii] = f2pack(CEM2 * a, CEM2 * a);
        XC1[ii] = f2pack(CEM2 * b, CEM2 * b);
        XC2[ii] = f2pack(CEM2 * c, CEM2 * c);
        P0[ii]  = f2pack(m0, m0);
        P1[ii]  = f2pack(m1, m1);
        P2[ii]  = f2pack(m2, m2);
    }

    // Accumulators per i: dcp (AC), sum w (SW), sum w*xj (SX).
    u64 AC0[IBLK], AC1[IBLK], AC2[IBLK], SW[IBLK], SX0[IBLK], SX1[IBLK], SX2[IBLK];
    #pragma unroll
    for (int ii = 0; ii < IBLK; ii++) {
        AC0[ii] = AC1[ii] = AC2[ii] = 0;
        SW[ii] = SX0[ii] = SX1[ii] = SX2[ii] = 0;
    }

    const int jquads = jcount >> 2;
    for (int q = 0; q < jquads; q++) {
        // Broadcast LDS.128: 4 consecutive j values per array.
        const ulonglong2 x0q = *(const ulonglong2*)&sxj0[4 * q];
        const ulonglong2 x1q = *(const ulonglong2*)&sxj1[4 * q];
        const ulonglong2 x2q = *(const ulonglong2*)&sxj2[4 * q];
        const ulonglong2 p0q = *(const ulonglong2*)&spj0[4 * q];
        const ulonglong2 p1q = *(const ulonglong2*)&spj1[4 * q];
        const ulonglong2 p2q = *(const ulonglong2*)&spj2[4 * q];
        const ulonglong2 cq  = *(const ulonglong2*)&scj[4 * q];

        #pragma unroll
        for (int h = 0; h < 2; h++) {
            const u64 xj0 = h ? x0q.y : x0q.x;
            const u64 xj1 = h ? x1q.y : x1q.x;
            const u64 xj2 = h ? x2q.y : x2q.x;
            const u64 pj0 = h ? p0q.y : p0q.x;
            const u64 pj1 = h ? p1q.y : p1q.x;
            const u64 pj2 = h ? p2q.y : p2q.x;
            const u64 cj  = h ? cq.y  : cq.x;

            #pragma unroll
            for (int ii = 0; ii < IBLK; ii++) {
                // targ = CE*d2 = (A_i + c_j) + sum_d CEM2*xi_d*xj_d
                u64 t = add2(A[ii], cj);
                t = fma2(XC0[ii], xj0, t);
                t = fma2(XC1[ii], xj1, t);
                t = fma2(XC2[ii], xj2, t);
                float tlo, thi;
                f2unpack(t, tlo, thi);
                const u64 e = f2pack(ex2(tlo), ex2(thi));

                u64 pd = mul2(P0[ii], pj0);
                pd = fma2(P1[ii], pj1, pd);
                pd = fma2(P2[ii], pj2, pd);
                const u64 w = mul2(e, pd);

                AC0[ii] = fma2(e, pj0, AC0[ii]);
                AC1[ii] = fma2(e, pj1, AC1[ii]);
                AC2[ii] = fma2(e, pj2, AC2[ii]);
                SW[ii]  = add2(SW[ii], w);
                SX0[ii] = fma2(w, xj0, SX0[ii]);
                SX1[ii] = fma2(w, xj1, SX1[ii]);
                SX2[ii] = fma2(w, xj2, SX2[ii]);
            }
        }
    }

    // Scalar tail (jcount % 4; empty for N=8192 with JTILE=360).
    float tA0[IBLK] = {}, tA1[IBLK] = {}, tA2[IBLK] = {};
    float tW[IBLK] = {}, tX0[IBLK] = {}, tX1[IBLK] = {}, tX2[IBLK] = {};
    for (int jj = jquads << 2; jj < jcount; jj++) {
        const float xj0 = sxj0[jj], xj1 = sxj1[jj], xj2 = sxj2[jj];
        const float pj0 = spj0[jj], pj1 = spj1[jj], pj2 = spj2[jj];
        const float cj = scj[jj];
        #pragma unroll
        for (int ii = 0; ii < IBLK; ii++) {
            float alo, ahi;
            f2unpack(A[ii], alo, ahi);
            float c0lo, c0hi, c1lo, c1hi, c2lo, c2hi;
            f2unpack(XC0[ii], c0lo, c0hi);
            f2unpack(XC1[ii], c1lo, c1hi);
            f2unpack(XC2[ii], c2lo, c2hi);
            float p0lo, p0hi, p1lo, p1hi, p2lo, p2hi;
            f2unpack(P0[ii], p0lo, p0hi);
            f2unpack(P1[ii], p1lo, p1hi);
            f2unpack(P2[ii], p2lo, p2hi);
            const float t = alo + cj + c0lo * xj0 + c1lo * xj1 + c2lo * xj2;
            const float e = ex2(t);
            const float pd = p0lo * pj0 + p1lo * pj1 + p2lo * pj2;
            const float w = e * pd;
            tA0[ii] += e * pj0;  tA1[ii] += e * pj1;  tA2[ii] += e * pj2;
            tW[ii] += w;  tX0[ii] += w * xj0;  tX1[ii] += w * xj1;  tX2[ii] += w * xj2;
        }
    }

    float* dcp = out + 3 * N;
    const float inv_sig2 = 100.0f;
    #pragma unroll
    for (int ii = 0; ii < IBLK; ii++) {
        const int i = ibase + ii * TPB;
        if (i >= N) continue;
        const float xi0 = x[3 * i + 0], xi1 = x[3 * i + 1], xi2 = x[3 * i + 2];
        float a, b;
        f2unpack(SW[ii], a, b);  const float sw = a + b + tW[ii];
        f2unpack(SX0[ii], a, b); const float s0 = a + b + tX0[ii];
        f2unpack(SX1[ii], a, b); const float s1 = a + b + tX1[ii];
        f2unpack(SX2[ii], a, b); const float s2 = a + b + tX2[ii];
        atomicAdd(&out[3 * i + 0], inv_sig2 * (xi0 * sw - s0));
        atomicAdd(&out[3 * i + 1], inv_sig2 * (xi1 * sw - s1));
        atomicAdd(&out[3 * i + 2], inv_sig2 * (xi2 * sw - s2));
        f2unpack(AC0[ii], a, b); atomicAdd(&dcp[3 * i + 0], a + b + tA0[ii]);
        f2unpack(AC1[ii], a, b); atomicAdd(&dcp[3 * i + 1], a + b + tA1[ii]);
        f2unpack(AC2[ii], a, b); atomicAdd(&dcp[3 * i + 2], a + b + tA2[ii]);
    }
}

extern "C" void kernel_launch(void* const* d_in, const int* in_sizes, int n_in,
                              void* d_out, int out_size) {
    const float* mom = (const float*)d_in[0];
    const float* x   = (const float*)d_in[1];
    float* out = (float*)d_out;
    const int N = in_sizes[0] / 3;

    zero_out_kernel<<<(out_size + 255) / 256, 256>>>(out, out_size);

    dim3 grid((N + TPB * IBLK - 1) / (TPB * IBLK), (N + JTILE - 1) / JTILE);
    lddmm_kernel<<<grid, TPB>>>(mom, x, out, N);
}